// round 1
// baseline (speedup 1.0000x reference)
#include <cuda_runtime.h>
#include <math.h>

#define NTOK 43520   // N * Lq = 8 * 5440
#define NBATCH 8
#define LQ 5440
#define DIM 256
#define NHEAD 8
#define HDIM 32
#define NLVL 4
#define NPT 4
#define DFFN 1024

// ---- scratch (static device globals; no allocation at runtime) ----
__device__ float g_query[(size_t)NTOK * DIM];     // src+pos, later reused as src2
__device__ float g_value[(size_t)NTOK * DIM];     // value proj, later reused as ffn out
__device__ float g_off[(size_t)NTOK * DIM];       // offset proj (NH*NL*NP*2 = 256)
__device__ float g_attn[(size_t)NTOK * 128];      // attn logits (NH*NL*NP = 128)
__device__ float g_attnout[(size_t)NTOK * DIM];   // deform-attn output
__device__ float g_x[(size_t)NTOK * DIM];         // after first LN
__device__ float g_hidden[(size_t)NTOK * DFFN];   // FFN hidden

// ---------------------------------------------------------------------------
// elementwise add: query = src + pos
// ---------------------------------------------------------------------------
__global__ void add_kernel(const float* __restrict__ a, const float* __restrict__ b,
                           float* __restrict__ o, int n) {
    int i = blockIdx.x * blockDim.x + threadIdx.x;
    if (i < n) o[i] = a[i] + b[i];
}

// ---------------------------------------------------------------------------
// classic 128x128x8 fp32 SGEMM, C = A(MxK) @ B(KxN) + bias, optional relu.
// Requires M%128==0, N%128==0, K%8==0 (true for all calls here).
// ---------------------------------------------------------------------------
__global__ __launch_bounds__(256)
void sgemm128(const float* __restrict__ A, const float* __restrict__ B,
              const float* __restrict__ bias, float* __restrict__ C,
              int M, int N, int K, int relu) {
    __shared__ float As[8][128];
    __shared__ float Bs[8][128];

    const int m0 = blockIdx.y * 128;
    const int n0 = blockIdx.x * 128;
    const int tid = threadIdx.x;

    const int ar = tid >> 1;            // 0..127
    const int ac = (tid & 1) * 4;       // 0 or 4
    const int br = tid >> 5;            // 0..7
    const int bc = (tid & 31) * 4;      // 0..124

    const int tr = (tid >> 4) << 3;     // row base 0..120
    const int tc = (tid & 15) << 3;     // col base 0..120

    float acc[8][8];
#pragma unroll
    for (int i = 0; i < 8; i++)
#pragma unroll
        for (int j = 0; j < 8; j++) acc[i][j] = 0.f;

    for (int k0 = 0; k0 < K; k0 += 8) {
        float4 av = *(const float4*)(A + (size_t)(m0 + ar) * K + k0 + ac);
        As[ac + 0][ar] = av.x;
        As[ac + 1][ar] = av.y;
        As[ac + 2][ar] = av.z;
        As[ac + 3][ar] = av.w;
        float4 bv = *(const float4*)(B + (size_t)(k0 + br) * N + n0 + bc);
        *(float4*)&Bs[br][bc] = bv;
        __syncthreads();

#pragma unroll
        for (int k = 0; k < 8; k++) {
            float ra[8], rb[8];
#pragma unroll
            for (int i = 0; i < 8; i++) ra[i] = As[k][tr + i];
#pragma unroll
            for (int j = 0; j < 8; j++) rb[j] = Bs[k][tc + j];
#pragma unroll
            for (int i = 0; i < 8; i++)
#pragma unroll
                for (int j = 0; j < 8; j++) acc[i][j] = fmaf(ra[i], rb[j], acc[i][j]);
        }
        __syncthreads();
    }

#pragma unroll
    for (int i = 0; i < 8; i++) {
#pragma unroll
        for (int j = 0; j < 8; j++) {
            float v = acc[i][j] + bias[n0 + tc + j];
            if (relu) v = fmaxf(v, 0.f);
            C[(size_t)(m0 + tr + i) * N + n0 + tc + j] = v;
        }
    }
}

// ---------------------------------------------------------------------------
// deformable attention sampling. One block per token (256 threads = 8 warps),
// one warp per head, lane = head-dim channel.
// ---------------------------------------------------------------------------
__global__ __launch_bounds__(256)
void deform_kernel(const float* __restrict__ refp) {
    const int m = blockIdx.x;            // token 0..NTOK-1
    const int h = threadIdx.x >> 5;      // head
    const int lane = threadIdx.x & 31;   // channel
    const int b = m / LQ;

    const int lvlH[NLVL] = {64, 32, 16, 8};
    const int lvlW[NLVL] = {64, 32, 16, 8};
    const int lvlS[NLVL] = {0, 4096, 5120, 5376};

    // softmax over 16 logits for this (token, head) — all lanes duplicate (broadcast loads)
    const float* logit = g_attn + (size_t)m * 128 + h * 16;
    float mx = -1e30f;
#pragma unroll
    for (int i = 0; i < 16; i++) mx = fmaxf(mx, logit[i]);
    float w[16];
    float sum = 0.f;
#pragma unroll
    for (int i = 0; i < 16; i++) { w[i] = expf(logit[i] - mx); sum += w[i]; }
    const float inv = 1.f / sum;

    const float* off = g_off + (size_t)m * 256 + h * 32;   // (NL, NP, 2)
    const float* rp = refp + (size_t)m * NLVL * 2;

    float acc = 0.f;
#pragma unroll
    for (int l = 0; l < NLVL; l++) {
        const int H = lvlH[l], W = lvlW[l], S = lvlS[l];
        const float rx = rp[l * 2 + 0];
        const float ry = rp[l * 2 + 1];
        const float invW = 1.f / (float)W;
        const float invH = 1.f / (float)H;
        const float* vbase = g_value + ((size_t)b * LQ + S) * DIM + h * HDIM + lane;
#pragma unroll
        for (int p = 0; p < NPT; p++) {
            const int oi = (l * NPT + p) * 2;
            const float lx = rx + off[oi + 0] * invW;
            const float ly = ry + off[oi + 1] * invH;
            const float x = lx * (float)W - 0.5f;
            const float y = ly * (float)H - 0.5f;
            const float x0f = floorf(x), y0f = floorf(y);
            const int x0 = (int)x0f, y0 = (int)y0f;
            const float wx1 = x - x0f, wy1 = y - y0f;
            const float wx0 = 1.f - wx1, wy0 = 1.f - wy1;

            float v00 = 0.f, v01 = 0.f, v10 = 0.f, v11 = 0.f;
            const bool xin0 = (x0 >= 0) & (x0 < W);
            const bool xin1 = (x0 + 1 >= 0) & (x0 + 1 < W);
            const bool yin0 = (y0 >= 0) & (y0 < H);
            const bool yin1 = (y0 + 1 >= 0) & (y0 + 1 < H);
            if (yin0 & xin0) v00 = vbase[(size_t)(y0 * W + x0) * DIM];
            if (yin0 & xin1) v01 = vbase[(size_t)(y0 * W + x0 + 1) * DIM];
            if (yin1 & xin0) v10 = vbase[(size_t)((y0 + 1) * W + x0) * DIM];
            if (yin1 & xin1) v11 = vbase[(size_t)((y0 + 1) * W + x0 + 1) * DIM];

            const float bil = (v00 * wx0 + v01 * wx1) * wy0 + (v10 * wx0 + v11 * wx1) * wy1;
            acc = fmaf(w[l * NPT + p] * inv, bil, acc);
        }
    }
    g_attnout[(size_t)m * DIM + h * HDIM + lane] = acc;
}

// ---------------------------------------------------------------------------
// fused residual + LayerNorm: out = LN(a + b) * gamma + beta. One block/token.
// ---------------------------------------------------------------------------
__global__ __launch_bounds__(256)
void ln_kernel(const float* __restrict__ a, const float* __restrict__ b,
               const float* __restrict__ gam, const float* __restrict__ bet,
               float* __restrict__ o) {
    __shared__ float sred[8];
    __shared__ float smu, svar;
    const int m = blockIdx.x;
    const int t = threadIdx.x;
    const size_t idx = (size_t)m * DIM + t;
    const float v = a[idx] + b[idx];

    float s = v;
#pragma unroll
    for (int off = 16; off > 0; off >>= 1) s += __shfl_xor_sync(0xffffffffu, s, off);
    if ((t & 31) == 0) sred[t >> 5] = s;
    __syncthreads();
    if (t == 0) {
        float tot = 0.f;
#pragma unroll
        for (int i = 0; i < 8; i++) tot += sred[i];
        smu = tot * (1.f / DIM);
    }
    __syncthreads();
    const float mu = smu;
    const float d = v - mu;

    s = d * d;
#pragma unroll
    for (int off = 16; off > 0; off >>= 1) s += __shfl_xor_sync(0xffffffffu, s, off);
    if ((t & 31) == 0) sred[t >> 5] = s;
    __syncthreads();
    if (t == 0) {
        float tot = 0.f;
#pragma unroll
        for (int i = 0; i < 8; i++) tot += sred[i];
        svar = tot * (1.f / DIM);
    }
    __syncthreads();

    o[idx] = d * rsqrtf(svar + 1e-5f) * gam[t] + bet[t];
}

// ---------------------------------------------------------------------------
// launch
// ---------------------------------------------------------------------------
extern "C" void kernel_launch(void* const* d_in, const int* in_sizes, int n_in,
                              void* d_out, int out_size) {
    const float* src    = (const float*)d_in[0];
    const float* pos    = (const float*)d_in[1];
    const float* refp   = (const float*)d_in[2];
    // d_in[3] = spatial_shapes (static, hardcoded)
    const float* W_value = (const float*)d_in[4];
    const float* b_value = (const float*)d_in[5];
    const float* W_off   = (const float*)d_in[6];
    const float* b_off   = (const float*)d_in[7];
    const float* W_attn  = (const float*)d_in[8];
    const float* b_attn  = (const float*)d_in[9];
    const float* W_out   = (const float*)d_in[10];
    const float* b_out   = (const float*)d_in[11];
    const float* ln1g    = (const float*)d_in[12];
    const float* ln1b    = (const float*)d_in[13];
    const float* W1      = (const float*)d_in[14];
    const float* b1      = (const float*)d_in[15];
    const float* W2      = (const float*)d_in[16];
    const float* b2      = (const float*)d_in[17];
    const float* ln2g    = (const float*)d_in[18];
    const float* ln2b    = (const float*)d_in[19];
    float* out = (float*)d_out;

    float *query, *value, *offs, *attn, *attnout, *x, *hidden;
    cudaGetSymbolAddress((void**)&query,   g_query);
    cudaGetSymbolAddress((void**)&value,   g_value);
    cudaGetSymbolAddress((void**)&offs,    g_off);
    cudaGetSymbolAddress((void**)&attn,    g_attn);
    cudaGetSymbolAddress((void**)&attnout, g_attnout);
    cudaGetSymbolAddress((void**)&x,       g_x);
    cudaGetSymbolAddress((void**)&hidden,  g_hidden);

    const int M = NTOK;
    const int nEl = NTOK * DIM;

    // query = src + pos
    add_kernel<<<(nEl + 255) / 256, 256>>>(src, pos, query, nEl);

    // projections
    {
        dim3 g(DIM / 128, M / 128);
        sgemm128<<<g, 256>>>(src, W_value, b_value, value, M, DIM, DIM, 0);
        sgemm128<<<g, 256>>>(query, W_off, b_off, offs, M, DIM, DIM, 0);
    }
    {
        dim3 g(128 / 128, M / 128);
        sgemm128<<<g, 256>>>(query, W_attn, b_attn, attn, M, 128, DIM, 0);
    }

    // deformable sampling + attention-weighted sum
    deform_kernel<<<M, 256>>>(refp);

    // output projection -> src2 (reuse query buffer)
    {
        dim3 g(DIM / 128, M / 128);
        sgemm128<<<g, 256>>>(attnout, W_out, b_out, query, M, DIM, DIM, 0);
    }

    // x = LN(src + src2)
    ln_kernel<<<M, 256>>>(src, query, ln1g, ln1b, x);

    // FFN
    {
        dim3 g(DFFN / 128, M / 128);
        sgemm128<<<g, 256>>>(x, W1, b1, hidden, M, DFFN, DIM, 1);
    }
    {
        dim3 g(DIM / 128, M / 128);
        sgemm128<<<g, 256>>>(hidden, W2, b2, value, M, DIM, DFFN, 0);  // reuse value buf
    }

    // out = LN(x + ffn)
    ln_kernel<<<M, 256>>>(x, value, ln2g, ln2b, out);
}

// round 4
// speedup vs baseline: 2.1332x; 2.1332x over previous
#include <cuda_runtime.h>
#include <math.h>
#include <stdint.h>

#define NTOK 43520   // N * Lq = 8 * 5440
#define LQ 5440
#define DIM 256
#define NHEAD 8
#define HDIM 32
#define NLVL 4
#define NPT 4
#define DFFN 1024

// ---- scratch (static device globals; no runtime allocation) ----
__device__ float g_query[(size_t)NTOK * DIM];
__device__ float g_value[(size_t)NTOK * DIM];
__device__ float g_off[(size_t)NTOK * DIM];
__device__ float g_attn[(size_t)NTOK * 128];
__device__ float g_attnout[(size_t)NTOK * DIM];
__device__ float g_x[(size_t)NTOK * DIM];
__device__ float g_hidden[(size_t)NTOK * DFFN];
// transposed weights (K-major per output row): Wt[n][k] = W[k][n]
__device__ float g_WvT[256 * 256];
__device__ float g_WoffT[256 * 256];
__device__ float g_WattnT[128 * 256];
__device__ float g_WoutT[256 * 256];
__device__ float g_W1T[1024 * 256];
__device__ float g_W2T[256 * 1024];

// ---------------------------------------------------------------------------
__device__ __forceinline__ uint32_t f2tf32(float f) {
    uint32_t u;
    asm("cvt.rna.tf32.f32 %0, %1;" : "=r"(u) : "f"(f));
    return u;
}

__device__ __forceinline__ void mma_tf32(float c[4], uint32_t a0, uint32_t a1,
                                         uint32_t a2, uint32_t a3,
                                         uint32_t b0, uint32_t b1) {
    asm volatile(
        "mma.sync.aligned.m16n8k8.row.col.f32.tf32.tf32.f32 "
        "{%0,%1,%2,%3}, {%4,%5,%6,%7}, {%8,%9}, {%0,%1,%2,%3};"
        : "+f"(c[0]), "+f"(c[1]), "+f"(c[2]), "+f"(c[3])
        : "r"(a0), "r"(a1), "r"(a2), "r"(a3), "r"(b0), "r"(b1));
}

// ---------------------------------------------------------------------------
// tf32 mma.sync GEMM: C[M,N] = A[M,K] @ Bt[N,K]^T + bias, optional relu.
// CTA tile 128x128, 256 threads (2x4 warps, warp tile 64x32), K-chunk 32.
// Double-buffered smem with register prefetch. Stride 36 floats (16B aligned,
// conflict-free for fragment LDS). dyn smem = 2 * 2 * 128*36*4 = 73728 B.
// ---------------------------------------------------------------------------
#define SSTR 36
#define CHUNK_F4 1024   // (128 rows * 32 cols) / 4

__global__ __launch_bounds__(256)
void tgemm(const float* __restrict__ A, const float* __restrict__ Bt,
           const float* __restrict__ bias, float* __restrict__ C,
           int M, int N, int K, int relu) {
    extern __shared__ float smem[];   // [2][2][128*SSTR] : stage, {A,B}
    const int tid = threadIdx.x, wid = tid >> 5, lane = tid & 31;
    const int m0 = blockIdx.y << 7, n0 = blockIdx.x << 7;
    const int warp_m = (wid & 1) * 64;   // 0 or 64
    const int warp_n = (wid >> 1) * 32;  // 0..96

    const int lr = lane >> 2;  // 0..7
    const int lc = lane & 3;   // 0..3

    float c[4][4][4];
#pragma unroll
    for (int i = 0; i < 4; i++)
#pragma unroll
        for (int j = 0; j < 4; j++)
#pragma unroll
            for (int q = 0; q < 4; q++) c[i][j][q] = 0.f;

    const int nk = K >> 5;
    const int rowstr = K >> 2;  // float4 per source row
    const int row = tid >> 1;            // 0..127 (2 float4/row per thread pass)
    // thread covers 4 float4 of A and 4 of B per chunk:
    // idx = tid + i*256, row = idx>>3, q = idx&7

    float4 ra[4], rb[4];
    {
        const float4* sa = (const float4*)(A + (size_t)m0 * K);
        const float4* sb = (const float4*)(Bt + (size_t)n0 * K);
#pragma unroll
        for (int i = 0; i < 4; i++) {
            int idx = tid + (i << 8);
            int r = idx >> 3, q = idx & 7;
            ra[i] = sa[(size_t)r * rowstr + q];
            rb[i] = sb[(size_t)r * rowstr + q];
        }
    }

    int s = 0;
    for (int kc = 0; kc < nk; kc++) {
        float* As = smem + s * (2 * 128 * SSTR);
        float* Bs = As + 128 * SSTR;
        // store prefetched regs (converted to tf32 bit patterns)
#pragma unroll
        for (int i = 0; i < 4; i++) {
            int idx = tid + (i << 8);
            int r = idx >> 3, q = idx & 7;
            uint4 va = make_uint4(f2tf32(ra[i].x), f2tf32(ra[i].y),
                                  f2tf32(ra[i].z), f2tf32(ra[i].w));
            uint4 vb = make_uint4(f2tf32(rb[i].x), f2tf32(rb[i].y),
                                  f2tf32(rb[i].z), f2tf32(rb[i].w));
            *(uint4*)(As + r * SSTR + (q << 2)) = va;
            *(uint4*)(Bs + r * SSTR + (q << 2)) = vb;
        }
        __syncthreads();

        // prefetch next chunk
        if (kc + 1 < nk) {
            const float4* sa = (const float4*)(A + (size_t)m0 * K + (size_t)(kc + 1) * 32);
            const float4* sb = (const float4*)(Bt + (size_t)n0 * K + (size_t)(kc + 1) * 32);
#pragma unroll
            for (int i = 0; i < 4; i++) {
                int idx = tid + (i << 8);
                int r = idx >> 3, q = idx & 7;
                ra[i] = sa[(size_t)r * rowstr + q];
                rb[i] = sb[(size_t)r * rowstr + q];
            }
        }

        // compute: 4 k-steps of 8
        const uint32_t* Au = (const uint32_t*)As;
        const uint32_t* Bu = (const uint32_t*)Bs;
#pragma unroll
        for (int ks = 0; ks < 4; ks++) {
            const int k0 = ks << 3;
            uint32_t af[4][4], bf[4][2];
#pragma unroll
            for (int i = 0; i < 4; i++) {
                const int r = warp_m + (i << 4) + lr;
                af[i][0] = Au[r * SSTR + k0 + lc];
                af[i][1] = Au[(r + 8) * SSTR + k0 + lc];
                af[i][2] = Au[r * SSTR + k0 + lc + 4];
                af[i][3] = Au[(r + 8) * SSTR + k0 + lc + 4];
            }
#pragma unroll
            for (int j = 0; j < 4; j++) {
                const int n = warp_n + (j << 3) + lr;
                bf[j][0] = Bu[n * SSTR + k0 + lc];
                bf[j][1] = Bu[n * SSTR + k0 + lc + 4];
            }
#pragma unroll
            for (int i = 0; i < 4; i++)
#pragma unroll
                for (int j = 0; j < 4; j++)
                    mma_tf32(c[i][j], af[i][0], af[i][1], af[i][2], af[i][3],
                             bf[j][0], bf[j][1]);
        }
        s ^= 1;
        __syncthreads();
    }

    // epilogue: accumulators straight to global (float2 pairs)
#pragma unroll
    for (int i = 0; i < 4; i++) {
        const int r0 = m0 + warp_m + (i << 4) + lr;
#pragma unroll
        for (int j = 0; j < 4; j++) {
            const int c0 = n0 + warp_n + (j << 3) + (lc << 1);
            const float b0 = bias[c0], b1 = bias[c0 + 1];
            float v0 = c[i][j][0] + b0, v1 = c[i][j][1] + b1;
            float v2 = c[i][j][2] + b0, v3 = c[i][j][3] + b1;
            if (relu) {
                v0 = fmaxf(v0, 0.f); v1 = fmaxf(v1, 0.f);
                v2 = fmaxf(v2, 0.f); v3 = fmaxf(v3, 0.f);
            }
            *(float2*)(C + (size_t)r0 * N + c0) = make_float2(v0, v1);
            *(float2*)(C + (size_t)(r0 + 8) * N + c0) = make_float2(v2, v3);
        }
    }
}

// ---------------------------------------------------------------------------
// 32x32 tiled transpose: out[c][r] = in[r][c]; R,C multiples of 32
// ---------------------------------------------------------------------------
__global__ __launch_bounds__(1024)
void transpose32(const float* __restrict__ in, float* __restrict__ out, int R, int C) {
    __shared__ float t[32][33];
    int r = blockIdx.y * 32 + threadIdx.y;
    int c = blockIdx.x * 32 + threadIdx.x;
    t[threadIdx.y][threadIdx.x] = in[(size_t)r * C + c];
    __syncthreads();
    int ro = blockIdx.x * 32 + threadIdx.y;
    int co = blockIdx.y * 32 + threadIdx.x;
    out[(size_t)ro * R + co] = t[threadIdx.x][threadIdx.y];
}

// ---------------------------------------------------------------------------
__global__ void add_kernel(const float* __restrict__ a, const float* __restrict__ b,
                           float* __restrict__ o, int n) {
    int i = blockIdx.x * blockDim.x + threadIdx.x;
    if (i < n) o[i] = a[i] + b[i];
}

// ---------------------------------------------------------------------------
// deformable attention sampling. One block/token, one warp/head, lane = channel.
// ---------------------------------------------------------------------------
__global__ __launch_bounds__(256)
void deform_kernel(const float* __restrict__ refp) {
    const int m = blockIdx.x;
    const int h = threadIdx.x >> 5;
    const int lane = threadIdx.x & 31;
    const int b = m / LQ;

    const int lvlH[NLVL] = {64, 32, 16, 8};
    const int lvlW[NLVL] = {64, 32, 16, 8};
    const int lvlS[NLVL] = {0, 4096, 5120, 5376};

    const float* logit = g_attn + (size_t)m * 128 + h * 16;
    float mx = -1e30f;
#pragma unroll
    for (int i = 0; i < 16; i++) mx = fmaxf(mx, logit[i]);
    float w[16];
    float sum = 0.f;
#pragma unroll
    for (int i = 0; i < 16; i++) { w[i] = expf(logit[i] - mx); sum += w[i]; }
    const float inv = 1.f / sum;

    const float* off = g_off + (size_t)m * 256 + h * 32;
    const float* rp = refp + (size_t)m * NLVL * 2;

    float acc = 0.f;
#pragma unroll
    for (int l = 0; l < NLVL; l++) {
        const int H = lvlH[l], W = lvlW[l], S = lvlS[l];
        const float rx = rp[l * 2 + 0];
        const float ry = rp[l * 2 + 1];
        const float invW = 1.f / (float)W;
        const float invH = 1.f / (float)H;
        const float* vbase = g_value + ((size_t)b * LQ + S) * DIM + h * HDIM + lane;
#pragma unroll
        for (int p = 0; p < NPT; p++) {
            const int oi = (l * NPT + p) * 2;
            const float lx = rx + off[oi + 0] * invW;
            const float ly = ry + off[oi + 1] * invH;
            const float x = lx * (float)W - 0.5f;
            const float y = ly * (float)H - 0.5f;
            const float x0f = floorf(x), y0f = floorf(y);
            const int x0 = (int)x0f, y0 = (int)y0f;
            const float wx1 = x - x0f, wy1 = y - y0f;
            const float wx0 = 1.f - wx1, wy0 = 1.f - wy1;

            float v00 = 0.f, v01 = 0.f, v10 = 0.f, v11 = 0.f;
            const bool xin0 = (x0 >= 0) & (x0 < W);
            const bool xin1 = (x0 + 1 >= 0) & (x0 + 1 < W);
            const bool yin0 = (y0 >= 0) & (y0 < H);
            const bool yin1 = (y0 + 1 >= 0) & (y0 + 1 < H);
            if (yin0 & xin0) v00 = vbase[(size_t)(y0 * W + x0) * DIM];
            if (yin0 & xin1) v01 = vbase[(size_t)(y0 * W + x0 + 1) * DIM];
            if (yin1 & xin0) v10 = vbase[(size_t)((y0 + 1) * W + x0) * DIM];
            if (yin1 & xin1) v11 = vbase[(size_t)((y0 + 1) * W + x0 + 1) * DIM];

            const float bil = (v00 * wx0 + v01 * wx1) * wy0 + (v10 * wx0 + v11 * wx1) * wy1;
            acc = fmaf(w[l * NPT + p] * inv, bil, acc);
        }
    }
    g_attnout[(size_t)m * DIM + h * HDIM + lane] = acc;
}

// ---------------------------------------------------------------------------
// fused residual + LayerNorm
// ---------------------------------------------------------------------------
__global__ __launch_bounds__(256)
void ln_kernel(const float* __restrict__ a, const float* __restrict__ b,
               const float* __restrict__ gam, const float* __restrict__ bet,
               float* __restrict__ o) {
    __shared__ float sred[8];
    __shared__ float smu, svar;
    const int m = blockIdx.x;
    const int t = threadIdx.x;
    const size_t idx = (size_t)m * DIM + t;
    const float v = a[idx] + b[idx];

    float s = v;
#pragma unroll
    for (int off = 16; off > 0; off >>= 1) s += __shfl_xor_sync(0xffffffffu, s, off);
    if ((t & 31) == 0) sred[t >> 5] = s;
    __syncthreads();
    if (t == 0) {
        float tot = 0.f;
#pragma unroll
        for (int i = 0; i < 8; i++) tot += sred[i];
        smu = tot * (1.f / DIM);
    }
    __syncthreads();
    const float mu = smu;
    const float d = v - mu;

    s = d * d;
#pragma unroll
    for (int off = 16; off > 0; off >>= 1) s += __shfl_xor_sync(0xffffffffu, s, off);
    if ((t & 31) == 0) sred[t >> 5] = s;
    __syncthreads();
    if (t == 0) {
        float tot = 0.f;
#pragma unroll
        for (int i = 0; i < 8; i++) tot += sred[i];
        svar = tot * (1.f / DIM);
    }
    __syncthreads();

    o[idx] = d * rsqrtf(svar + 1e-5f) * gam[t] + bet[t];
}

// ---------------------------------------------------------------------------
extern "C" void kernel_launch(void* const* d_in, const int* in_sizes, int n_in,
                              void* d_out, int out_size) {
    const float* src    = (const float*)d_in[0];
    const float* pos    = (const float*)d_in[1];
    const float* refp   = (const float*)d_in[2];
    const float* W_value = (const float*)d_in[4];
    const float* b_value = (const float*)d_in[5];
    const float* W_off   = (const float*)d_in[6];
    const float* b_off   = (const float*)d_in[7];
    const float* W_attn  = (const float*)d_in[8];
    const float* b_attn  = (const float*)d_in[9];
    const float* W_out   = (const float*)d_in[10];
    const float* b_out   = (const float*)d_in[11];
    const float* ln1g    = (const float*)d_in[12];
    const float* ln1b    = (const float*)d_in[13];
    const float* W1      = (const float*)d_in[14];
    const float* b1      = (const float*)d_in[15];
    const float* W2      = (const float*)d_in[16];
    const float* b2      = (const float*)d_in[17];
    const float* ln2g    = (const float*)d_in[18];
    const float* ln2b    = (const float*)d_in[19];
    float* out = (float*)d_out;

    float *query, *value, *offs, *attn, *attnout, *x, *hidden;
    float *WvT, *WoffT, *WattnT, *WoutT, *W1T, *W2T;
    cudaGetSymbolAddress((void**)&query,   g_query);
    cudaGetSymbolAddress((void**)&value,   g_value);
    cudaGetSymbolAddress((void**)&offs,    g_off);
    cudaGetSymbolAddress((void**)&attn,    g_attn);
    cudaGetSymbolAddress((void**)&attnout, g_attnout);
    cudaGetSymbolAddress((void**)&x,       g_x);
    cudaGetSymbolAddress((void**)&hidden,  g_hidden);
    cudaGetSymbolAddress((void**)&WvT,   g_WvT);
    cudaGetSymbolAddress((void**)&WoffT, g_WoffT);
    cudaGetSymbolAddress((void**)&WattnT, g_WattnT);
    cudaGetSymbolAddress((void**)&WoutT, g_WoutT);
    cudaGetSymbolAddress((void**)&W1T,   g_W1T);
    cudaGetSymbolAddress((void**)&W2T,   g_W2T);

    const int SMEM = 2 * 2 * 128 * SSTR * 4;  // 73728
    cudaFuncSetAttribute(tgemm, cudaFuncAttributeMaxDynamicSharedMemorySize, SMEM);

    const int M = NTOK;
    const int nEl = NTOK * DIM;

    // transpose weights to K-major
    { dim3 b(32, 32);
      transpose32<<<dim3(8, 8),  b>>>(W_value, WvT,   256, 256);
      transpose32<<<dim3(8, 8),  b>>>(W_off,   WoffT, 256, 256);
      transpose32<<<dim3(4, 8),  b>>>(W_attn,  WattnT, 256, 128);
      transpose32<<<dim3(8, 8),  b>>>(W_out,   WoutT, 256, 256);
      transpose32<<<dim3(32, 8), b>>>(W1,      W1T,   256, 1024);
      transpose32<<<dim3(8, 32), b>>>(W2,      W2T,   1024, 256);
    }

    // query = src + pos
    add_kernel<<<(nEl + 255) / 256, 256>>>(src, pos, query, nEl);

    // projections (tensor cores, tf32 mma.sync)
    tgemm<<<dim3(2, M / 128), 256, SMEM>>>(src,   WvT,   b_value, value, M, DIM, DIM, 0);
    tgemm<<<dim3(2, M / 128), 256, SMEM>>>(query, WoffT, b_off,   offs,  M, DIM, DIM, 0);
    tgemm<<<dim3(1, M / 128), 256, SMEM>>>(query, WattnT, b_attn, attn,  M, 128, DIM, 0);

    // deformable sampling + attention-weighted sum
    deform_kernel<<<M, 256>>>(refp);

    // output projection -> src2 (reuse query buffer)
    tgemm<<<dim3(2, M / 128), 256, SMEM>>>(attnout, WoutT, b_out, query, M, DIM, DIM, 0);

    // x = LN(src + src2)
    ln_kernel<<<M, 256>>>(src, query, ln1g, ln1b, x);

    // FFN
    tgemm<<<dim3(8, M / 128), 256, SMEM>>>(x,      W1T, b1, hidden, M, DFFN, DIM, 1);
    tgemm<<<dim3(2, M / 128), 256, SMEM>>>(hidden, W2T, b2, value,  M, DIM, DFFN, 0);

    // out = LN(x + ffn)
    ln_kernel<<<M, 256>>>(x, value, ln2g, ln2b, out);
}

// round 5
// speedup vs baseline: 2.5150x; 1.1790x over previous
#include <cuda_runtime.h>
#include <math.h>
#include <stdint.h>

#define NTOK 43520   // N * Lq = 8 * 5440
#define LQ 5440
#define DIM 256
#define NHEAD 8
#define HDIM 32
#define NLVL 4
#define NPT 4
#define DFFN 1024

// ---- scratch (static device globals; no runtime allocation) ----
__device__ float g_query[(size_t)NTOK * DIM];
__device__ float g_value[(size_t)NTOK * DIM];
__device__ float g_oa[(size_t)NTOK * 384];      // fused offsets(256)+attn logits(128)
__device__ float g_attnout[(size_t)NTOK * DIM];
__device__ float g_x[(size_t)NTOK * DIM];
__device__ float g_hidden[(size_t)NTOK * DFFN];
// transposed (K-major) tf32-rounded weights
__device__ float g_WvT[256 * 256];
__device__ float g_WoaT[384 * 256];             // rows 0..255 = W_off^T, 256..383 = W_attn^T
__device__ float g_WoutT[256 * 256];
__device__ float g_W1T[1024 * 256];
__device__ float g_W2T[256 * 1024];
__device__ float g_boa[384];

// ---------------------------------------------------------------------------
__device__ __forceinline__ uint32_t s2u(const void* p) {
    uint32_t a;
    asm("{ .reg .u64 t; cvta.to.shared.u64 t, %1; cvt.u32.u64 %0, t; }" : "=r"(a) : "l"(p));
    return a;
}

__device__ __forceinline__ uint32_t f2tf32(float f) {
    uint32_t u;
    asm("cvt.rna.tf32.f32 %0, %1;" : "=r"(u) : "f"(f));
    return u;
}

__device__ __forceinline__ void cp16(uint32_t dst, const void* src) {
    asm volatile("cp.async.cg.shared.global [%0], [%1], 16;" :: "r"(dst), "l"(src));
}

__device__ __forceinline__ void mma_tf32(float c[4], uint32_t a0, uint32_t a1,
                                         uint32_t a2, uint32_t a3,
                                         uint32_t b0, uint32_t b1) {
    asm volatile(
        "mma.sync.aligned.m16n8k8.row.col.f32.tf32.tf32.f32 "
        "{%0,%1,%2,%3}, {%4,%5,%6,%7}, {%8,%9}, {%0,%1,%2,%3};"
        : "+f"(c[0]), "+f"(c[1]), "+f"(c[2]), "+f"(c[3])
        : "r"(a0), "r"(a1), "r"(a2), "r"(a3), "r"(b0), "r"(b1));
}

// ---------------------------------------------------------------------------
// tf32 mma.sync GEMM: C[M,N] = A[M,K] @ Bt[N,K]^T + bias, optional relu.
// CTA tile 128x128, 256 threads (2x4 warps, warp tile 64x32), K-chunk 32.
// cp.async double-buffered smem (A truncated to tf32 by HW; Bt pre-rounded).
// dyn smem = 2 * 2 * 128 * 36 * 4 = 73728 B.
// ---------------------------------------------------------------------------
#define SSTR 36
#define STAGE_F (2 * 128 * SSTR)     // floats per stage (A then B)
#define STAGE_B (STAGE_F * 4)        // 36864 bytes
#define BOFF_B (128 * SSTR * 4)      // 18432 bytes

__global__ __launch_bounds__(256)
void tgemm(const float* __restrict__ A, const float* __restrict__ Bt,
           const float* __restrict__ bias, float* __restrict__ C,
           int M, int N, int K, int relu) {
    extern __shared__ float smem[];
    const uint32_t sb = s2u(smem);
    const int tid = threadIdx.x, wid = tid >> 5, lane = tid & 31;
    const int m0 = blockIdx.y << 7, n0 = blockIdx.x << 7;
    const int warp_m = (wid & 1) * 64;
    const int warp_n = (wid >> 1) * 32;
    const int lr = lane >> 2;
    const int lc = lane & 3;

    float c[4][4][4];
#pragma unroll
    for (int i = 0; i < 4; i++)
#pragma unroll
        for (int j = 0; j < 4; j++)
#pragma unroll
            for (int q = 0; q < 4; q++) c[i][j][q] = 0.f;

    const int nk = K >> 5;
    const int rowstr = K >> 2;
    const float4* Abase = (const float4*)(A + (size_t)m0 * K);
    const float4* Bbase = (const float4*)(Bt + (size_t)n0 * K);

    // issue one K-chunk of A+B into stage s
    const int r_ = tid >> 3, q_ = tid & 7;   // thread's first (row, f4) slot
#define ISSUE(s, kc)                                                          \
    {                                                                         \
        const uint32_t so = sb + (uint32_t)(s) * STAGE_B;                     \
        _Pragma("unroll")                                                     \
        for (int i = 0; i < 4; i++) {                                         \
            const int r = r_ + (i << 5);                                      \
            const uint32_t off = ((uint32_t)(r * SSTR + (q_ << 2))) << 2;     \
            cp16(so + off, Abase + (size_t)r * rowstr + (kc) * 8 + q_);       \
            cp16(so + BOFF_B + off, Bbase + (size_t)r * rowstr + (kc) * 8 + q_);\
        }                                                                     \
        asm volatile("cp.async.commit_group;" ::: "memory");                  \
    }

    ISSUE(0, 0);
    int s = 0;
    for (int kc = 0; kc < nk; kc++) {
        if (kc + 1 < nk) {
            ISSUE(s ^ 1, kc + 1);
            asm volatile("cp.async.wait_group 1;" ::: "memory");
        } else {
            asm volatile("cp.async.wait_group 0;" ::: "memory");
        }
        __syncthreads();

        const uint32_t* Au = (const uint32_t*)(smem + s * STAGE_F);
        const uint32_t* Bu = Au + 128 * SSTR;
#pragma unroll
        for (int ks = 0; ks < 4; ks++) {
            const int k0 = ks << 3;
            uint32_t af[4][4], bf[4][2];
#pragma unroll
            for (int i = 0; i < 4; i++) {
                const int r = warp_m + (i << 4) + lr;
                af[i][0] = Au[r * SSTR + k0 + lc];
                af[i][1] = Au[(r + 8) * SSTR + k0 + lc];
                af[i][2] = Au[r * SSTR + k0 + lc + 4];
                af[i][3] = Au[(r + 8) * SSTR + k0 + lc + 4];
            }
#pragma unroll
            for (int j = 0; j < 4; j++) {
                const int n = warp_n + (j << 3) + lr;
                bf[j][0] = Bu[n * SSTR + k0 + lc];
                bf[j][1] = Bu[n * SSTR + k0 + lc + 4];
            }
#pragma unroll
            for (int i = 0; i < 4; i++)
#pragma unroll
                for (int j = 0; j < 4; j++)
                    mma_tf32(c[i][j], af[i][0], af[i][1], af[i][2], af[i][3],
                             bf[j][0], bf[j][1]);
        }
        s ^= 1;
        __syncthreads();
    }

    // epilogue: accumulators straight to global (float2 pairs)
#pragma unroll
    for (int i = 0; i < 4; i++) {
        const int r0 = m0 + warp_m + (i << 4) + lr;
#pragma unroll
        for (int j = 0; j < 4; j++) {
            const int c0 = n0 + warp_n + (j << 3) + (lc << 1);
            const float b0 = bias[c0], b1 = bias[c0 + 1];
            float v0 = c[i][j][0] + b0, v1 = c[i][j][1] + b1;
            float v2 = c[i][j][2] + b0, v3 = c[i][j][3] + b1;
            if (relu) {
                v0 = fmaxf(v0, 0.f); v1 = fmaxf(v1, 0.f);
                v2 = fmaxf(v2, 0.f); v3 = fmaxf(v3, 0.f);
            }
            *(float2*)(C + (size_t)r0 * N + c0) = make_float2(v0, v1);
            *(float2*)(C + (size_t)(r0 + 8) * N + c0) = make_float2(v2, v3);
        }
    }
}

// ---------------------------------------------------------------------------
// prep: all weight transposes (+ tf32 rna round) + bias concat, one kernel.
// 1024 threads/block; 737 blocks total.
// ---------------------------------------------------------------------------
__device__ __forceinline__ void tr_tile(float t[32][33],
                                        const float* __restrict__ in,
                                        float* __restrict__ out,
                                        int C_in, int out_stride,
                                        int tx, int ty, int orow_off) {
    const int tyid = threadIdx.x >> 5, txid = threadIdx.x & 31;
    float v = in[(size_t)(ty * 32 + tyid) * C_in + tx * 32 + txid];
    t[tyid][txid] = __uint_as_float(f2tf32(v));
    __syncthreads();
    out[(size_t)(orow_off + tx * 32 + tyid) * out_stride + ty * 32 + txid] = t[txid][tyid];
}

__global__ __launch_bounds__(1024)
void prep_w(const float* __restrict__ Wv, const float* __restrict__ Woff,
            const float* __restrict__ Wattn, const float* __restrict__ Wout,
            const float* __restrict__ W1, const float* __restrict__ W2,
            const float* __restrict__ boff, const float* __restrict__ battn) {
    __shared__ float t[32][33];
    const int b = blockIdx.x;
    if (b < 64) {
        tr_tile(t, Wv, g_WvT, 256, 256, b & 7, b >> 3, 0);
    } else if (b < 128) {
        const int l = b - 64;
        tr_tile(t, Woff, g_WoaT, 256, 256, l & 7, l >> 3, 0);
    } else if (b < 160) {
        const int l = b - 128;
        tr_tile(t, Wattn, g_WoaT, 128, 256, l & 3, l >> 2, 256);
    } else if (b < 224) {
        const int l = b - 160;
        tr_tile(t, Wout, g_WoutT, 256, 256, l & 7, l >> 3, 0);
    } else if (b < 480) {
        const int l = b - 224;
        tr_tile(t, W1, g_W1T, 1024, 256, l & 31, l >> 5, 0);
    } else if (b < 736) {
        const int l = b - 480;
        tr_tile(t, W2, g_W2T, 256, 1024, l & 7, l >> 3, 0);
    } else {
        const int tid = threadIdx.x;
        if (tid < 256) g_boa[tid] = boff[tid];
        else if (tid < 384) g_boa[tid] = battn[tid - 256];
    }
}

// ---------------------------------------------------------------------------
__global__ void add_kernel(const float4* __restrict__ a, const float4* __restrict__ b,
                           float4* __restrict__ o, int n4) {
    int i = blockIdx.x * blockDim.x + threadIdx.x;
    if (i < n4) {
        float4 x = a[i], y = b[i];
        o[i] = make_float4(x.x + y.x, x.y + y.y, x.z + y.z, x.w + y.w);
    }
}

// ---------------------------------------------------------------------------
// deformable attention sampling. One block/token, one warp/head, lane = channel.
// ---------------------------------------------------------------------------
__global__ __launch_bounds__(256)
void deform_kernel(const float* __restrict__ refp) {
    const int m = blockIdx.x;
    const int h = threadIdx.x >> 5;
    const int lane = threadIdx.x & 31;
    const int b = m / LQ;

    const int lvlH[NLVL] = {64, 32, 16, 8};
    const int lvlW[NLVL] = {64, 32, 16, 8};
    const int lvlS[NLVL] = {0, 4096, 5120, 5376};

    const float* logit = g_oa + (size_t)m * 384 + 256 + h * 16;
    float mx = -1e30f;
#pragma unroll
    for (int i = 0; i < 16; i++) mx = fmaxf(mx, logit[i]);
    float w[16];
    float sum = 0.f;
#pragma unroll
    for (int i = 0; i < 16; i++) { w[i] = expf(logit[i] - mx); sum += w[i]; }
    const float inv = 1.f / sum;

    const float* off = g_oa + (size_t)m * 384 + h * 32;
    const float* rp = refp + (size_t)m * NLVL * 2;

    float acc = 0.f;
#pragma unroll
    for (int l = 0; l < NLVL; l++) {
        const int H = lvlH[l], W = lvlW[l], S = lvlS[l];
        const float rx = rp[l * 2 + 0];
        const float ry = rp[l * 2 + 1];
        const float invW = 1.f / (float)W;
        const float invH = 1.f / (float)H;
        const float* vbase = g_value + ((size_t)b * LQ + S) * DIM + h * HDIM + lane;
#pragma unroll
        for (int p = 0; p < NPT; p++) {
            const int oi = (l * NPT + p) * 2;
            const float lx = rx + off[oi + 0] * invW;
            const float ly = ry + off[oi + 1] * invH;
            const float x = lx * (float)W - 0.5f;
            const float y = ly * (float)H - 0.5f;
            const float x0f = floorf(x), y0f = floorf(y);
            const int x0 = (int)x0f, y0 = (int)y0f;
            const float wx1 = x - x0f, wy1 = y - y0f;
            const float wx0 = 1.f - wx1, wy0 = 1.f - wy1;

            float v00 = 0.f, v01 = 0.f, v10 = 0.f, v11 = 0.f;
            const bool xin0 = (x0 >= 0) & (x0 < W);
            const bool xin1 = (x0 + 1 >= 0) & (x0 + 1 < W);
            const bool yin0 = (y0 >= 0) & (y0 < H);
            const bool yin1 = (y0 + 1 >= 0) & (y0 + 1 < H);
            if (yin0 & xin0) v00 = vbase[(size_t)(y0 * W + x0) * DIM];
            if (yin0 & xin1) v01 = vbase[(size_t)(y0 * W + x0 + 1) * DIM];
            if (yin1 & xin0) v10 = vbase[(size_t)((y0 + 1) * W + x0) * DIM];
            if (yin1 & xin1) v11 = vbase[(size_t)((y0 + 1) * W + x0 + 1) * DIM];

            const float bil = (v00 * wx0 + v01 * wx1) * wy0 + (v10 * wx0 + v11 * wx1) * wy1;
            acc = fmaf(w[l * NPT + p] * inv, bil, acc);
        }
    }
    g_attnout[(size_t)m * DIM + h * HDIM + lane] = acc;
}

// ---------------------------------------------------------------------------
// fused residual + LayerNorm
// ---------------------------------------------------------------------------
__global__ __launch_bounds__(256)
void ln_kernel(const float* __restrict__ a, const float* __restrict__ b,
               const float* __restrict__ gam, const float* __restrict__ bet,
               float* __restrict__ o) {
    __shared__ float sred[8];
    __shared__ float smu, svar;
    const int m = blockIdx.x;
    const int t = threadIdx.x;
    const size_t idx = (size_t)m * DIM + t;
    const float v = a[idx] + b[idx];

    float s = v;
#pragma unroll
    for (int off = 16; off > 0; off >>= 1) s += __shfl_xor_sync(0xffffffffu, s, off);
    if ((t & 31) == 0) sred[t >> 5] = s;
    __syncthreads();
    if (t == 0) {
        float tot = 0.f;
#pragma unroll
        for (int i = 0; i < 8; i++) tot += sred[i];
        smu = tot * (1.f / DIM);
    }
    __syncthreads();
    const float mu = smu;
    const float d = v - mu;

    s = d * d;
#pragma unroll
    for (int off = 16; off > 0; off >>= 1) s += __shfl_xor_sync(0xffffffffu, s, off);
    if ((t & 31) == 0) sred[t >> 5] = s;
    __syncthreads();
    if (t == 0) {
        float tot = 0.f;
#pragma unroll
        for (int i = 0; i < 8; i++) tot += sred[i];
        svar = tot * (1.f / DIM);
    }
    __syncthreads();

    o[idx] = d * rsqrtf(svar + 1e-5f) * gam[t] + bet[t];
}

// ---------------------------------------------------------------------------
extern "C" void kernel_launch(void* const* d_in, const int* in_sizes, int n_in,
                              void* d_out, int out_size) {
    const float* src    = (const float*)d_in[0];
    const float* pos    = (const float*)d_in[1];
    const float* refp   = (const float*)d_in[2];
    const float* W_value = (const float*)d_in[4];
    const float* b_value = (const float*)d_in[5];
    const float* W_off   = (const float*)d_in[6];
    const float* b_off   = (const float*)d_in[7];
    const float* W_attn  = (const float*)d_in[8];
    const float* b_attn  = (const float*)d_in[9];
    const float* W_out   = (const float*)d_in[10];
    const float* b_out   = (const float*)d_in[11];
    const float* ln1g    = (const float*)d_in[12];
    const float* ln1b    = (const float*)d_in[13];
    const float* W1      = (const float*)d_in[14];
    const float* b1      = (const float*)d_in[15];
    const float* W2      = (const float*)d_in[16];
    const float* b2      = (const float*)d_in[17];
    const float* ln2g    = (const float*)d_in[18];
    const float* ln2b    = (const float*)d_in[19];
    float* out = (float*)d_out;

    float *query, *value, *oa, *attnout, *x, *hidden;
    float *WvT, *WoaT, *WoutT, *W1T, *W2T, *boa;
    cudaGetSymbolAddress((void**)&query,   g_query);
    cudaGetSymbolAddress((void**)&value,   g_value);
    cudaGetSymbolAddress((void**)&oa,      g_oa);
    cudaGetSymbolAddress((void**)&attnout, g_attnout);
    cudaGetSymbolAddress((void**)&x,       g_x);
    cudaGetSymbolAddress((void**)&hidden,  g_hidden);
    cudaGetSymbolAddress((void**)&WvT,   g_WvT);
    cudaGetSymbolAddress((void**)&WoaT,  g_WoaT);
    cudaGetSymbolAddress((void**)&WoutT, g_WoutT);
    cudaGetSymbolAddress((void**)&W1T,   g_W1T);
    cudaGetSymbolAddress((void**)&W2T,   g_W2T);
    cudaGetSymbolAddress((void**)&boa,   g_boa);

    const int SMEM = 2 * STAGE_B;   // 73728
    cudaFuncSetAttribute(tgemm, cudaFuncAttributeMaxDynamicSharedMemorySize, SMEM);

    const int M = NTOK;
    const int n4 = NTOK * DIM / 4;

    // 1: weight prep (transpose + tf32 round + bias concat)
    prep_w<<<737, 1024>>>(W_value, W_off, W_attn, W_out, W1, W2, b_off, b_attn);

    // 2: query = src + pos
    add_kernel<<<(n4 + 255) / 256, 256>>>((const float4*)src, (const float4*)pos,
                                          (float4*)query, n4);

    // 3: value projection
    tgemm<<<dim3(2, M / 128), 256, SMEM>>>(src, WvT, b_value, value, M, DIM, DIM, 0);
    // 4: fused offsets+attn projection (N=384)
    tgemm<<<dim3(3, M / 128), 256, SMEM>>>(query, WoaT, boa, oa, M, 384, DIM, 0);

    // 5: deformable sampling + attention-weighted sum
    deform_kernel<<<M, 256>>>(refp);

    // 6: output projection -> src2 (reuse query buffer)  [ncu capture slot]
    tgemm<<<dim3(2, M / 128), 256, SMEM>>>(attnout, WoutT, b_out, query, M, DIM, DIM, 0);

    // 7: x = LN(src + src2)
    ln_kernel<<<M, 256>>>(src, query, ln1g, ln1b, x);

    // 8-9: FFN
    tgemm<<<dim3(8, M / 128), 256, SMEM>>>(x,      W1T, b1, hidden, M, DFFN, DIM, 1);
    tgemm<<<dim3(2, M / 128), 256, SMEM>>>(hidden, W2T, b2, value,  M, DIM, DFFN, 0);

    // 10: out = LN(x + ffn)
    ln_kernel<<<M, 256>>>(x, value, ln2g, ln2b, out);
}